// round 3
// baseline (speedup 1.0000x reference)
#include <cuda_runtime.h>
#include <cuda_bf16.h>

#define N_NODES 100000
#define N_EDGES 1600000
#define IN_F 128
#define OUT_F 32
#define HEADS 2
#define NHF 64  // HEADS*OUT_F

// ---- scratch (device globals; no allocation) ----
__device__ float g_feat[N_NODES * NHF];   // [N][H][F] = [N][64]
__device__ float g_el[N_NODES * HEADS];
__device__ float g_er[N_NODES * HEADS];
__device__ float g_a[N_NODES];
__device__ float g_b[N_NODES];
__device__ float g_vfold[NHF];
__device__ float g_cfold;
// CSR-by-dst scratch
__device__ int g_deg[N_NODES];
__device__ int g_cur[N_NODES];
__device__ int g_off[N_NODES + 1];
__device__ int g_srcs[N_EDGES];

// ---- fold MLP: v = W1@W2, c = b1@W2 + b2 ----
__global__ void k_fold(const float* __restrict__ W1, const float* __restrict__ b1,
                       const float* __restrict__ W2, const float* __restrict__ b2) {
    int t = threadIdx.x;
    if (t < NHF) {
        float v = 0.f;
        #pragma unroll
        for (int j = 0; j < OUT_F; ++j) v += W1[t * OUT_F + j] * W2[j];
        g_vfold[t] = v;
    }
    if (t == 0) {
        float c = b2[0];
        for (int j = 0; j < OUT_F; ++j) c += b1[j] * W2[j];
        g_cfold = c;
    }
}

// ---- zero degree counters ----
__global__ void k_zero_deg() {
    int i = blockIdx.x * blockDim.x + threadIdx.x;
    if (i < N_NODES) g_deg[i] = 0;
}

// ---- histogram of dst ----
__global__ void k_hist(const int* __restrict__ dst) {
    int e = blockIdx.x * blockDim.x + threadIdx.x;
    if (e < N_EDGES) atomicAdd(&g_deg[dst[e]], 1);
}

// ---- exclusive scan of g_deg -> g_off, g_cur (single block, 1024 thr) ----
__global__ void k_scan() {
    __shared__ int s[1024];
    const int t = threadIdx.x;
    const int PER = (N_NODES + 1023) / 1024;  // 98
    const int base = t * PER;
    int sum = 0;
    for (int i = 0; i < PER; ++i) {
        int idx = base + i;
        if (idx < N_NODES) sum += g_deg[idx];
    }
    s[t] = sum;
    __syncthreads();
    for (int off = 1; off < 1024; off <<= 1) {
        int v = (t >= off) ? s[t - off] : 0;
        __syncthreads();
        s[t] += v;
        __syncthreads();
    }
    int run = (t == 0) ? 0 : s[t - 1];
    for (int i = 0; i < PER; ++i) {
        int idx = base + i;
        if (idx < N_NODES) {
            int d = g_deg[idx];
            g_off[idx] = run;
            g_cur[idx] = run;
            run += d;
        }
    }
    if (t == 1023) g_off[N_NODES] = s[1023];
}

// ---- scatter src ids into dst-sorted order ----
__global__ void k_scatter(const int* __restrict__ src, const int* __restrict__ dst) {
    int e = blockIdx.x * blockDim.x + threadIdx.x;
    if (e >= N_EDGES) return;
    int p = atomicAdd(&g_cur[dst[e]], 1);
    g_srcs[p] = src[e];
}

// ---- feat = x @ W : [100000,128]x[128,64], tiled GEMM BM=64,BN=64,BK=64 ----
__global__ void k_gemm(const float* __restrict__ x, const float* __restrict__ W) {
    __shared__ float Xs[64][68];
    __shared__ float Ws[64][64];
    const int block_row = blockIdx.x * 64;
    const int t = threadIdx.x;         // 128 threads
    const int tx = t & 15;
    const int ty = t >> 4;
    float acc[8][4];
    #pragma unroll
    for (int r = 0; r < 8; ++r)
        #pragma unroll
        for (int c = 0; c < 4; ++c) acc[r][c] = 0.f;

    for (int kt = 0; kt < 2; ++kt) {
        #pragma unroll
        for (int i = t; i < 64 * 16; i += 128) {
            int row = i >> 4, kq = i & 15;
            int gr = block_row + row;
            float4 v = make_float4(0.f, 0.f, 0.f, 0.f);
            if (gr < N_NODES)
                v = *(const float4*)&x[gr * IN_F + kt * 64 + kq * 4];
            Xs[kq * 4 + 0][row] = v.x;
            Xs[kq * 4 + 1][row] = v.y;
            Xs[kq * 4 + 2][row] = v.z;
            Xs[kq * 4 + 3][row] = v.w;
        }
        #pragma unroll
        for (int i = t; i < 64 * 16; i += 128) {
            int kk = i >> 4, nq = i & 15;
            *(float4*)&Ws[kk][nq * 4] =
                *(const float4*)&W[(kt * 64 + kk) * NHF + nq * 4];
        }
        __syncthreads();
        #pragma unroll 16
        for (int k = 0; k < 64; ++k) {
            float4 wv = *(const float4*)&Ws[k][tx * 4];
            float4 x0 = *(const float4*)&Xs[k][ty * 8];
            float4 x1 = *(const float4*)&Xs[k][ty * 8 + 4];
            float xr[8] = {x0.x, x0.y, x0.z, x0.w, x1.x, x1.y, x1.z, x1.w};
            #pragma unroll
            for (int r = 0; r < 8; ++r) {
                acc[r][0] += xr[r] * wv.x;
                acc[r][1] += xr[r] * wv.y;
                acc[r][2] += xr[r] * wv.z;
                acc[r][3] += xr[r] * wv.w;
            }
        }
        __syncthreads();
    }
    #pragma unroll
    for (int r = 0; r < 8; ++r) {
        int gr = block_row + ty * 8 + r;
        if (gr < N_NODES)
            *(float4*)&g_feat[gr * NHF + tx * 4] =
                make_float4(acc[r][0], acc[r][1], acc[r][2], acc[r][3]);
    }
}

// ---- per-node: el/er attention dots. one warp per node ----
__global__ void k_node1(const float* __restrict__ attn_l, const float* __restrict__ attn_r) {
    int warp = (blockIdx.x * blockDim.x + threadIdx.x) >> 5;
    int lane = threadIdx.x & 31;
    if (warp >= N_NODES) return;
    int n = warp;
    float f0 = g_feat[n * NHF + lane];        // head 0
    float f1 = g_feat[n * NHF + 32 + lane];   // head 1
    float el0 = f0 * attn_l[lane];
    float el1 = f1 * attn_l[32 + lane];
    float er0 = f0 * attn_r[lane];
    float er1 = f1 * attn_r[32 + lane];
    #pragma unroll
    for (int o = 16; o > 0; o >>= 1) {
        el0 += __shfl_xor_sync(0xFFFFFFFFu, el0, o);
        el1 += __shfl_xor_sync(0xFFFFFFFFu, el1, o);
        er0 += __shfl_xor_sync(0xFFFFFFFFu, er0, o);
        er1 += __shfl_xor_sync(0xFFFFFFFFu, er1, o);
    }
    if (lane == 0) {
        g_el[n * 2] = el0; g_el[n * 2 + 1] = el1;
        g_er[n * 2] = er0; g_er[n * 2 + 1] = er1;
    }
}

// ---- fused per-dst-node: softmax + aggregation + epilogue (warp per node) ----
// rst = sum(ex_i * feat_i) / sum(ex_i)   (normalization is linear -> one pass)
__global__ void k_agg(const float* __restrict__ bias_gat) {
    int warp = (blockIdx.x * blockDim.x + threadIdx.x) >> 5;
    int lane = threadIdx.x & 31;
    if (warp >= N_NODES) return;
    const int n = warp;
    const int beg = g_off[n];
    const int end = g_off[n + 1];

    float2 erd = *(const float2*)&g_er[n * 2];  // broadcast load
    float acc0 = 0.f, acc1 = 0.f, den0 = 0.f, den1 = 0.f;

    int s = (beg < end) ? g_srcs[beg] : 0;
    for (int i = beg; i < end; ++i) {
        int s_next = (i + 1 < end) ? g_srcs[i + 1] : 0;
        float2 exv;
        if (lane == 0) {
            float2 els = *(const float2*)&g_el[s * 2];
            float v0 = els.x + erd.x;
            float v1 = els.y + erd.y;
            v0 = v0 > 0.f ? v0 : 0.2f * v0;
            v1 = v1 > 0.f ? v1 : 0.2f * v1;
            exv = make_float2(__expf(v0), __expf(v1));
        }
        exv.x = __shfl_sync(0xFFFFFFFFu, exv.x, 0);
        exv.y = __shfl_sync(0xFFFFFFFFu, exv.y, 0);
        float f0 = g_feat[s * NHF + lane];
        float f1 = g_feat[s * NHF + 32 + lane];
        acc0 = fmaf(exv.x, f0, acc0);
        acc1 = fmaf(exv.y, f1, acc1);
        den0 += exv.x;
        den1 += exv.y;
        s = s_next;
    }

    float r0 = (den0 > 0.f) ? acc0 / den0 : 0.f;
    float r1 = (den1 > 0.f) ? acc1 / den1 : 0.f;
    float r = (r0 + bias_gat[lane] + r1 + bias_gat[32 + lane]) * 0.5f;
    float h = fmaxf(r, 0.f);
    float av = h * g_vfold[lane];
    float bv = h * g_vfold[32 + lane];
    #pragma unroll
    for (int o = 16; o > 0; o >>= 1) {
        av += __shfl_xor_sync(0xFFFFFFFFu, av, o);
        bv += __shfl_xor_sync(0xFFFFFFFFu, bv, o);
    }
    if (lane == 0) { g_a[n] = av; g_b[n] = bv; }
}

// ---- per-edge final score ----
__global__ void k_edge_score(const int* __restrict__ src, const int* __restrict__ dst,
                             float* __restrict__ out) {
    int e = blockIdx.x * blockDim.x + threadIdx.x;
    if (e >= N_EDGES) return;
    out[e] = g_a[src[e]] + g_b[dst[e]] + g_cfold;
}

extern "C" void kernel_launch(void* const* d_in, const int* in_sizes, int n_in,
                              void* d_out, int out_size) {
    const float* x       = (const float*)d_in[0];
    const float* W       = (const float*)d_in[1];
    const float* attn_l  = (const float*)d_in[2];
    const float* attn_r  = (const float*)d_in[3];
    const float* bias_gat= (const float*)d_in[4];
    const float* W1      = (const float*)d_in[5];
    const float* b1      = (const float*)d_in[6];
    const float* W2      = (const float*)d_in[7];
    const float* b2      = (const float*)d_in[8];
    const int*   src     = (const int*)d_in[9];
    const int*   dst     = (const int*)d_in[10];
    float* out = (float*)d_out;

    k_zero_deg<<<(N_NODES + 255) / 256, 256>>>();
    k_fold<<<1, 64>>>(W1, b1, W2, b2);
    k_hist<<<(N_EDGES + 255) / 256, 256>>>(dst);
    k_scan<<<1, 1024>>>();
    k_scatter<<<(N_EDGES + 255) / 256, 256>>>(src, dst);
    k_gemm<<<(N_NODES + 63) / 64, 128>>>(x, W);
    k_node1<<<(N_NODES * 32 + 255) / 256, 256>>>(attn_l, attn_r);
    k_agg<<<(N_NODES * 32 + 255) / 256, 256>>>(bias_gat);
    k_edge_score<<<(N_EDGES + 255) / 256, 256>>>(src, dst, out);
}

// round 6
// speedup vs baseline: 1.6776x; 1.6776x over previous
#include <cuda_runtime.h>
#include <cuda_bf16.h>

#define N_NODES 100000
#define N_EDGES 1600000
#define IN_F 128
#define OUT_F 32
#define HEADS 2
#define NHF 64  // HEADS*OUT_F
#define SCAN_BLK 1024
#define N_SCAN_BLKS ((N_NODES + SCAN_BLK - 1) / SCAN_BLK)  // 98

// ---- scratch (device globals; no allocation) ----
__device__ float g_feat[N_NODES * NHF];   // [N][H][F] = [N][64]
__device__ float g_el[N_NODES * HEADS];
__device__ float g_er[N_NODES * HEADS];
__device__ float g_a[N_NODES];
__device__ float g_b[N_NODES];
__device__ float g_vfold[NHF];
__device__ float g_cfold;
// CSR-by-dst scratch
__device__ int g_deg[N_NODES];
__device__ int g_cur[N_NODES];
__device__ int g_off[N_NODES + 1];
__device__ int g_srcs[N_EDGES];
__device__ int g_blksum[N_SCAN_BLKS];

// ---- fold MLP: v = W1@W2, c = b1@W2 + b2 ----
__global__ void k_fold(const float* __restrict__ W1, const float* __restrict__ b1,
                       const float* __restrict__ W2, const float* __restrict__ b2) {
    int t = threadIdx.x;
    if (t < NHF) {
        float v = 0.f;
        #pragma unroll
        for (int j = 0; j < OUT_F; ++j) v += W1[t * OUT_F + j] * W2[j];
        g_vfold[t] = v;
    }
    if (t == 0) {
        float c = b2[0];
        for (int j = 0; j < OUT_F; ++j) c += b1[j] * W2[j];
        g_cfold = c;
    }
}

// ---- zero degree counters ----
__global__ void k_zero_deg() {
    int i = blockIdx.x * blockDim.x + threadIdx.x;
    if (i < N_NODES) g_deg[i] = 0;
}

// ---- histogram of dst ----
__global__ void k_hist(const int* __restrict__ dst) {
    int e = blockIdx.x * blockDim.x + threadIdx.x;
    if (e < N_EDGES) atomicAdd(&g_deg[dst[e]], 1);
}

// ---- scan phase 1: per-block sums of g_deg ----
__global__ void k_scan1() {
    __shared__ int s[SCAN_BLK];
    int i = blockIdx.x * SCAN_BLK + threadIdx.x;
    s[threadIdx.x] = (i < N_NODES) ? g_deg[i] : 0;
    __syncthreads();
    #pragma unroll
    for (int off = SCAN_BLK / 2; off > 0; off >>= 1) {
        if (threadIdx.x < off) s[threadIdx.x] += s[threadIdx.x + off];
        __syncthreads();
    }
    if (threadIdx.x == 0) g_blksum[blockIdx.x] = s[0];
}

// ---- scan phase 2: exclusive scan of the 98 block sums (1 block, 128 thr) ----
__global__ void k_scan2() {
    __shared__ int s[128];
    int t = threadIdx.x;
    int v = (t < N_SCAN_BLKS) ? g_blksum[t] : 0;
    s[t] = v;
    __syncthreads();
    #pragma unroll
    for (int off = 1; off < 128; off <<= 1) {
        int u = (t >= off) ? s[t - off] : 0;
        __syncthreads();
        s[t] += u;
        __syncthreads();
    }
    if (t < N_SCAN_BLKS) g_blksum[t] = s[t] - v;  // exclusive prefix
    if (t == 127) g_off[N_NODES] = s[127];        // total edge count
}

// ---- scan phase 3: in-block exclusive scan + block offset -> g_off, g_cur ----
__global__ void k_scan3() {
    __shared__ int s[SCAN_BLK];
    int i = blockIdx.x * SCAN_BLK + threadIdx.x;
    int v = (i < N_NODES) ? g_deg[i] : 0;
    s[threadIdx.x] = v;
    __syncthreads();
    #pragma unroll
    for (int off = 1; off < SCAN_BLK; off <<= 1) {
        int u = (threadIdx.x >= off) ? s[threadIdx.x - off] : 0;
        __syncthreads();
        s[threadIdx.x] += u;
        __syncthreads();
    }
    if (i < N_NODES) {
        int excl = g_blksum[blockIdx.x] + s[threadIdx.x] - v;
        g_off[i] = excl;
        g_cur[i] = excl;
    }
}

// ---- scatter src ids into dst-sorted order ----
__global__ void k_scatter(const int* __restrict__ src, const int* __restrict__ dst) {
    int e = blockIdx.x * blockDim.x + threadIdx.x;
    if (e >= N_EDGES) return;
    int p = atomicAdd(&g_cur[dst[e]], 1);
    g_srcs[p] = src[e];
}

// ---- feat = x @ W, fused with el/er attention dots in the epilogue ----
__global__ void k_gemm(const float* __restrict__ x, const float* __restrict__ W,
                       const float* __restrict__ attn_l, const float* __restrict__ attn_r) {
    __shared__ float Xs[64][68];
    __shared__ float Ws[64][64];
    const int block_row = blockIdx.x * 64;
    const int t = threadIdx.x;         // 128 threads
    const int tx = t & 15;
    const int ty = t >> 4;
    float acc[8][4];
    #pragma unroll
    for (int r = 0; r < 8; ++r)
        #pragma unroll
        for (int c = 0; c < 4; ++c) acc[r][c] = 0.f;

    for (int kt = 0; kt < 2; ++kt) {
        #pragma unroll
        for (int i = t; i < 64 * 16; i += 128) {
            int row = i >> 4, kq = i & 15;
            int gr = block_row + row;
            float4 v = make_float4(0.f, 0.f, 0.f, 0.f);
            if (gr < N_NODES)
                v = *(const float4*)&x[gr * IN_F + kt * 64 + kq * 4];
            Xs[kq * 4 + 0][row] = v.x;
            Xs[kq * 4 + 1][row] = v.y;
            Xs[kq * 4 + 2][row] = v.z;
            Xs[kq * 4 + 3][row] = v.w;
        }
        #pragma unroll
        for (int i = t; i < 64 * 16; i += 128) {
            int kk = i >> 4, nq = i & 15;
            *(float4*)&Ws[kk][nq * 4] =
                *(const float4*)&W[(kt * 64 + kk) * NHF + nq * 4];
        }
        __syncthreads();
        #pragma unroll 16
        for (int k = 0; k < 64; ++k) {
            float4 wv = *(const float4*)&Ws[k][tx * 4];
            float4 x0 = *(const float4*)&Xs[k][ty * 8];
            float4 x1 = *(const float4*)&Xs[k][ty * 8 + 4];
            float xr[8] = {x0.x, x0.y, x0.z, x0.w, x1.x, x1.y, x1.z, x1.w};
            #pragma unroll
            for (int r = 0; r < 8; ++r) {
                acc[r][0] += xr[r] * wv.x;
                acc[r][1] += xr[r] * wv.y;
                acc[r][2] += xr[r] * wv.z;
                acc[r][3] += xr[r] * wv.w;
            }
        }
        __syncthreads();
    }
    // epilogue: write feat, and compute partial el/er dots per thread
    float4 al = *(const float4*)&attn_l[tx * 4];
    float4 ar = *(const float4*)&attn_r[tx * 4];
    float pel[8], per[8];
    #pragma unroll
    for (int r = 0; r < 8; ++r) {
        int gr = block_row + ty * 8 + r;
        if (gr < N_NODES)
            *(float4*)&g_feat[gr * NHF + tx * 4] =
                make_float4(acc[r][0], acc[r][1], acc[r][2], acc[r][3]);
        pel[r] = acc[r][0] * al.x + acc[r][1] * al.y + acc[r][2] * al.z + acc[r][3] * al.w;
        per[r] = acc[r][0] * ar.x + acc[r][1] * ar.y + acc[r][2] * ar.z + acc[r][3] * ar.w;
    }
    // reduce across the 8 lanes covering one head (tx 0-7 = head0, 8-15 = head1)
    #pragma unroll
    for (int o = 1; o < 8; o <<= 1) {
        #pragma unroll
        for (int r = 0; r < 8; ++r) {
            pel[r] += __shfl_xor_sync(0xFFFFFFFFu, pel[r], o);
            per[r] += __shfl_xor_sync(0xFFFFFFFFu, per[r], o);
        }
    }
    if ((tx & 7) == 0) {
        int h = tx >> 3;
        #pragma unroll
        for (int r = 0; r < 8; ++r) {
            int gr = block_row + ty * 8 + r;
            if (gr < N_NODES) {
                g_el[gr * 2 + h] = pel[r];
                g_er[gr * 2 + h] = per[r];
            }
        }
    }
}

// ---- fused per-dst-node: softmax + aggregation + epilogue (warp per node) ----
__global__ void k_agg(const float* __restrict__ bias_gat) {
    int warp = (blockIdx.x * blockDim.x + threadIdx.x) >> 5;
    int lane = threadIdx.x & 31;
    if (warp >= N_NODES) return;
    const int n = warp;
    const int beg = g_off[n];
    const int end = g_off[n + 1];

    float2 erd = *(const float2*)&g_er[n * 2];
    float acc0 = 0.f, acc1 = 0.f, den0 = 0.f, den1 = 0.f;

    int s = (beg < end) ? g_srcs[beg] : 0;
    for (int i = beg; i < end; ++i) {
        int s_next = (i + 1 < end) ? g_srcs[i + 1] : 0;
        float2 exv;
        if (lane == 0) {
            float2 els = *(const float2*)&g_el[s * 2];
            float v0 = els.x + erd.x;
            float v1 = els.y + erd.y;
            v0 = v0 > 0.f ? v0 : 0.2f * v0;
            v1 = v1 > 0.f ? v1 : 0.2f * v1;
            exv = make_float2(__expf(v0), __expf(v1));
        }
        exv.x = __shfl_sync(0xFFFFFFFFu, exv.x, 0);
        exv.y = __shfl_sync(0xFFFFFFFFu, exv.y, 0);
        float f0 = g_feat[s * NHF + lane];
        float f1 = g_feat[s * NHF + 32 + lane];
        acc0 = fmaf(exv.x, f0, acc0);
        acc1 = fmaf(exv.y, f1, acc1);
        den0 += exv.x;
        den1 += exv.y;
        s = s_next;
    }

    float r0 = (den0 > 0.f) ? acc0 / den0 : 0.f;
    float r1 = (den1 > 0.f) ? acc1 / den1 : 0.f;
    float r = (r0 + bias_gat[lane] + r1 + bias_gat[32 + lane]) * 0.5f;
    float h = fmaxf(r, 0.f);
    float av = h * g_vfold[lane];
    float bv = h * g_vfold[32 + lane];
    #pragma unroll
    for (int o = 16; o > 0; o >>= 1) {
        av += __shfl_xor_sync(0xFFFFFFFFu, av, o);
        bv += __shfl_xor_sync(0xFFFFFFFFu, bv, o);
    }
    if (lane == 0) { g_a[n] = av; g_b[n] = bv; }
}

// ---- per-edge final score ----
__global__ void k_edge_score(const int* __restrict__ src, const int* __restrict__ dst,
                             float* __restrict__ out) {
    int e = blockIdx.x * blockDim.x + threadIdx.x;
    if (e >= N_EDGES) return;
    out[e] = g_a[src[e]] + g_b[dst[e]] + g_cfold;
}

extern "C" void kernel_launch(void* const* d_in, const int* in_sizes, int n_in,
                              void* d_out, int out_size) {
    const float* x       = (const float*)d_in[0];
    const float* W       = (const float*)d_in[1];
    const float* attn_l  = (const float*)d_in[2];
    const float* attn_r  = (const float*)d_in[3];
    const float* bias_gat= (const float*)d_in[4];
    const float* W1      = (const float*)d_in[5];
    const float* b1      = (const float*)d_in[6];
    const float* W2      = (const float*)d_in[7];
    const float* b2      = (const float*)d_in[8];
    const int*   src     = (const int*)d_in[9];
    const int*   dst     = (const int*)d_in[10];
    float* out = (float*)d_out;

    k_zero_deg<<<(N_NODES + 255) / 256, 256>>>();
    k_fold<<<1, 64>>>(W1, b1, W2, b2);
    k_hist<<<(N_EDGES + 255) / 256, 256>>>(dst);
    k_scan1<<<N_SCAN_BLKS, SCAN_BLK>>>();
    k_scan2<<<1, 128>>>();
    k_scan3<<<N_SCAN_BLKS, SCAN_BLK>>>();
    k_scatter<<<(N_EDGES + 255) / 256, 256>>>(src, dst);
    k_gemm<<<(N_NODES + 63) / 64, 128>>>(x, W, attn_l, attn_r);
    k_agg<<<(N_NODES * 32 + 255) / 256, 256>>>(bias_gat);
    k_edge_score<<<(N_EDGES + 255) / 256, 256>>>(src, dst, out);
}

// round 7
// speedup vs baseline: 1.9905x; 1.1865x over previous
#include <cuda_runtime.h>
#include <cuda_bf16.h>

#define N_NODES 100000
#define N_EDGES 1600000
#define IN_F 128
#define OUT_F 32
#define HEADS 2
#define NHF 64  // HEADS*OUT_F
#define SCAN_BLK 1024
#define N_SCAN_BLKS ((N_NODES + SCAN_BLK - 1) / SCAN_BLK)  // 98

// ---- scratch (device globals; no allocation) ----
__device__ float g_feat[N_NODES * NHF];   // [N][H][F] = [N][64]
__device__ float g_el[N_NODES * HEADS];
__device__ float g_er[N_NODES * HEADS];
__device__ float g_a[N_NODES];
__device__ float g_b[N_NODES];
__device__ float g_vfold[NHF];
__device__ float g_cfold;
// CSR-by-dst scratch
__device__ int g_deg[N_NODES];
__device__ int g_cur[N_NODES];
__device__ int g_off[N_NODES + 1];
__device__ int g_srcs[N_EDGES];
__device__ int g_blksum[N_SCAN_BLKS];

// ---- zero degree counters + fold MLP (block 0 does the fold) ----
__global__ void k_zero_fold(const float* __restrict__ W1, const float* __restrict__ b1,
                            const float* __restrict__ W2, const float* __restrict__ b2) {
    int i = blockIdx.x * blockDim.x + threadIdx.x;
    if (i < N_NODES) g_deg[i] = 0;
    if (blockIdx.x == 0) {
        int t = threadIdx.x;
        if (t < NHF) {
            float v = 0.f;
            #pragma unroll
            for (int j = 0; j < OUT_F; ++j) v += W1[t * OUT_F + j] * W2[j];
            g_vfold[t] = v;
        }
        if (t == 0) {
            float c = b2[0];
            for (int j = 0; j < OUT_F; ++j) c += b1[j] * W2[j];
            g_cfold = c;
        }
    }
}

// ---- histogram of dst (4 edges per thread, int4 loads) ----
__global__ void k_hist(const int* __restrict__ dst) {
    int i = blockIdx.x * blockDim.x + threadIdx.x;
    if (i * 4 >= N_EDGES) return;
    int4 d = *(const int4*)&dst[i * 4];
    atomicAdd(&g_deg[d.x], 1);
    atomicAdd(&g_deg[d.y], 1);
    atomicAdd(&g_deg[d.z], 1);
    atomicAdd(&g_deg[d.w], 1);
}

// ---- scan phase 1: per-block sums of g_deg ----
__global__ void k_scan1() {
    __shared__ int s[SCAN_BLK];
    int i = blockIdx.x * SCAN_BLK + threadIdx.x;
    s[threadIdx.x] = (i < N_NODES) ? g_deg[i] : 0;
    __syncthreads();
    #pragma unroll
    for (int off = SCAN_BLK / 2; off > 0; off >>= 1) {
        if (threadIdx.x < off) s[threadIdx.x] += s[threadIdx.x + off];
        __syncthreads();
    }
    if (threadIdx.x == 0) g_blksum[blockIdx.x] = s[0];
}

// ---- scan phase 2: exclusive scan of the 98 block sums (1 block, 128 thr) ----
__global__ void k_scan2() {
    __shared__ int s[128];
    int t = threadIdx.x;
    int v = (t < N_SCAN_BLKS) ? g_blksum[t] : 0;
    s[t] = v;
    __syncthreads();
    #pragma unroll
    for (int off = 1; off < 128; off <<= 1) {
        int u = (t >= off) ? s[t - off] : 0;
        __syncthreads();
        s[t] += u;
        __syncthreads();
    }
    if (t < N_SCAN_BLKS) g_blksum[t] = s[t] - v;  // exclusive prefix
    if (t == 127) g_off[N_NODES] = s[127];        // total edge count
}

// ---- scan phase 3: in-block exclusive scan + block offset -> g_off, g_cur ----
__global__ void k_scan3() {
    __shared__ int s[SCAN_BLK];
    int i = blockIdx.x * SCAN_BLK + threadIdx.x;
    int v = (i < N_NODES) ? g_deg[i] : 0;
    s[threadIdx.x] = v;
    __syncthreads();
    #pragma unroll
    for (int off = 1; off < SCAN_BLK; off <<= 1) {
        int u = (threadIdx.x >= off) ? s[threadIdx.x - off] : 0;
        __syncthreads();
        s[threadIdx.x] += u;
        __syncthreads();
    }
    if (i < N_NODES) {
        int excl = g_blksum[blockIdx.x] + s[threadIdx.x] - v;
        g_off[i] = excl;
        g_cur[i] = excl;
    }
}

// ---- scatter src ids into dst-sorted order (4 edges per thread) ----
__global__ void k_scatter(const int* __restrict__ src, const int* __restrict__ dst) {
    int i = blockIdx.x * blockDim.x + threadIdx.x;
    if (i * 4 >= N_EDGES) return;
    int4 s = *(const int4*)&src[i * 4];
    int4 d = *(const int4*)&dst[i * 4];
    g_srcs[atomicAdd(&g_cur[d.x], 1)] = s.x;
    g_srcs[atomicAdd(&g_cur[d.y], 1)] = s.y;
    g_srcs[atomicAdd(&g_cur[d.z], 1)] = s.z;
    g_srcs[atomicAdd(&g_cur[d.w], 1)] = s.w;
}

// ---- feat = x @ W, fused with el/er attention dots in the epilogue ----
__global__ void k_gemm(const float* __restrict__ x, const float* __restrict__ W,
                       const float* __restrict__ attn_l, const float* __restrict__ attn_r) {
    __shared__ float Xs[64][68];
    __shared__ float Ws[64][64];
    const int block_row = blockIdx.x * 64;
    const int t = threadIdx.x;         // 128 threads
    const int tx = t & 15;
    const int ty = t >> 4;
    float acc[8][4];
    #pragma unroll
    for (int r = 0; r < 8; ++r)
        #pragma unroll
        for (int c = 0; c < 4; ++c) acc[r][c] = 0.f;

    for (int kt = 0; kt < 2; ++kt) {
        #pragma unroll
        for (int i = t; i < 64 * 16; i += 128) {
            int row = i >> 4, kq = i & 15;
            int gr = block_row + row;
            float4 v = make_float4(0.f, 0.f, 0.f, 0.f);
            if (gr < N_NODES)
                v = *(const float4*)&x[gr * IN_F + kt * 64 + kq * 4];
            Xs[kq * 4 + 0][row] = v.x;
            Xs[kq * 4 + 1][row] = v.y;
            Xs[kq * 4 + 2][row] = v.z;
            Xs[kq * 4 + 3][row] = v.w;
        }
        #pragma unroll
        for (int i = t; i < 64 * 16; i += 128) {
            int kk = i >> 4, nq = i & 15;
            *(float4*)&Ws[kk][nq * 4] =
                *(const float4*)&W[(kt * 64 + kk) * NHF + nq * 4];
        }
        __syncthreads();
        #pragma unroll 16
        for (int k = 0; k < 64; ++k) {
            float4 wv = *(const float4*)&Ws[k][tx * 4];
            float4 x0 = *(const float4*)&Xs[k][ty * 8];
            float4 x1 = *(const float4*)&Xs[k][ty * 8 + 4];
            float xr[8] = {x0.x, x0.y, x0.z, x0.w, x1.x, x1.y, x1.z, x1.w};
            #pragma unroll
            for (int r = 0; r < 8; ++r) {
                acc[r][0] += xr[r] * wv.x;
                acc[r][1] += xr[r] * wv.y;
                acc[r][2] += xr[r] * wv.z;
                acc[r][3] += xr[r] * wv.w;
            }
        }
        __syncthreads();
    }
    // epilogue: write feat, and compute partial el/er dots per thread
    float4 al = *(const float4*)&attn_l[tx * 4];
    float4 ar = *(const float4*)&attn_r[tx * 4];
    float pel[8], per[8];
    #pragma unroll
    for (int r = 0; r < 8; ++r) {
        int gr = block_row + ty * 8 + r;
        if (gr < N_NODES)
            *(float4*)&g_feat[gr * NHF + tx * 4] =
                make_float4(acc[r][0], acc[r][1], acc[r][2], acc[r][3]);
        pel[r] = acc[r][0] * al.x + acc[r][1] * al.y + acc[r][2] * al.z + acc[r][3] * al.w;
        per[r] = acc[r][0] * ar.x + acc[r][1] * ar.y + acc[r][2] * ar.z + acc[r][3] * ar.w;
    }
    // reduce across the 8 lanes covering one head (tx 0-7 = head0, 8-15 = head1)
    #pragma unroll
    for (int o = 1; o < 8; o <<= 1) {
        #pragma unroll
        for (int r = 0; r < 8; ++r) {
            pel[r] += __shfl_xor_sync(0xFFFFFFFFu, pel[r], o);
            per[r] += __shfl_xor_sync(0xFFFFFFFFu, per[r], o);
        }
    }
    if ((tx & 7) == 0) {
        int h = tx >> 3;
        #pragma unroll
        for (int r = 0; r < 8; ++r) {
            int gr = block_row + ty * 8 + r;
            if (gr < N_NODES) {
                g_el[gr * 2 + h] = pel[r];
                g_er[gr * 2 + h] = per[r];
            }
        }
    }
}

// ---- fused per-dst-node: softmax + aggregation + epilogue (warp per node) ----
// Chunked: 32 edges' exp computed in parallel (one per lane), then a tight
// broadcast+fma loop with no MUFU and no single-lane serialization.
__global__ void k_agg(const float* __restrict__ bias_gat) {
    int warp = (blockIdx.x * blockDim.x + threadIdx.x) >> 5;
    int lane = threadIdx.x & 31;
    if (warp >= N_NODES) return;
    const int n = warp;
    const int beg = g_off[n];
    const int end = g_off[n + 1];

    const float2 erd = *(const float2*)&g_er[n * 2];
    float acc0 = 0.f, acc1 = 0.f, den0 = 0.f, den1 = 0.f;

    for (int base = beg; base < end; base += 32) {
        const int cnt = min(32, end - base);
        // phase 1: each lane computes exp for one edge of this chunk
        int s = 0;
        float ex0 = 0.f, ex1 = 0.f;
        if (lane < cnt) {
            s = g_srcs[base + lane];
            float2 els = *(const float2*)&g_el[s * 2];
            float v0 = els.x + erd.x;
            float v1 = els.y + erd.y;
            v0 = v0 > 0.f ? v0 : 0.2f * v0;
            v1 = v1 > 0.f ? v1 : 0.2f * v1;
            ex0 = __expf(v0);
            ex1 = __expf(v1);
        }
        // phase 2: broadcast each edge, accumulate weighted feat
        for (int j = 0; j < cnt; ++j) {
            int sj = __shfl_sync(0xFFFFFFFFu, s, j);
            float e0 = __shfl_sync(0xFFFFFFFFu, ex0, j);
            float e1 = __shfl_sync(0xFFFFFFFFu, ex1, j);
            float f0 = g_feat[sj * NHF + lane];
            float f1 = g_feat[sj * NHF + 32 + lane];
            acc0 = fmaf(e0, f0, acc0);
            acc1 = fmaf(e1, f1, acc1);
            den0 += e0;
            den1 += e1;
        }
    }

    float r0 = (den0 > 0.f) ? acc0 / den0 : 0.f;
    float r1 = (den1 > 0.f) ? acc1 / den1 : 0.f;
    float r = (r0 + bias_gat[lane] + r1 + bias_gat[32 + lane]) * 0.5f;
    float h = fmaxf(r, 0.f);
    float av = h * g_vfold[lane];
    float bv = h * g_vfold[32 + lane];
    #pragma unroll
    for (int o = 16; o > 0; o >>= 1) {
        av += __shfl_xor_sync(0xFFFFFFFFu, av, o);
        bv += __shfl_xor_sync(0xFFFFFFFFu, bv, o);
    }
    if (lane == 0) { g_a[n] = av; g_b[n] = bv; }
}

// ---- per-edge final score (4 edges per thread) ----
__global__ void k_edge_score(const int* __restrict__ src, const int* __restrict__ dst,
                             float* __restrict__ out) {
    int i = blockIdx.x * blockDim.x + threadIdx.x;
    if (i * 4 >= N_EDGES) return;
    int4 s = *(const int4*)&src[i * 4];
    int4 d = *(const int4*)&dst[i * 4];
    float c = g_cfold;
    float4 r;
    r.x = g_a[s.x] + g_b[d.x] + c;
    r.y = g_a[s.y] + g_b[d.y] + c;
    r.z = g_a[s.z] + g_b[d.z] + c;
    r.w = g_a[s.w] + g_b[d.w] + c;
    *(float4*)&out[i * 4] = r;
}

extern "C" void kernel_launch(void* const* d_in, const int* in_sizes, int n_in,
                              void* d_out, int out_size) {
    const float* x       = (const float*)d_in[0];
    const float* W       = (const float*)d_in[1];
    const float* attn_l  = (const float*)d_in[2];
    const float* attn_r  = (const float*)d_in[3];
    const float* bias_gat= (const float*)d_in[4];
    const float* W1      = (const float*)d_in[5];
    const float* b1      = (const float*)d_in[6];
    const float* W2      = (const float*)d_in[7];
    const float* b2      = (const float*)d_in[8];
    const int*   src     = (const int*)d_in[9];
    const int*   dst     = (const int*)d_in[10];
    float* out = (float*)d_out;

    k_zero_fold<<<(N_NODES + 255) / 256, 256>>>(W1, b1, W2, b2);
    k_hist<<<(N_EDGES / 4 + 255) / 256, 256>>>(dst);
    k_scan1<<<N_SCAN_BLKS, SCAN_BLK>>>();
    k_scan2<<<1, 128>>>();
    k_scan3<<<N_SCAN_BLKS, SCAN_BLK>>>();
    k_scatter<<<(N_EDGES / 4 + 255) / 256, 256>>>(src, dst);
    k_gemm<<<(N_NODES + 63) / 64, 128>>>(x, W, attn_l, attn_r);
    k_agg<<<(N_NODES * 32 + 255) / 256, 256>>>(bias_gat);
    k_edge_score<<<(N_EDGES / 4 + 255) / 256, 256>>>(src, dst, out);
}

// round 9
// speedup vs baseline: 2.0127x; 1.0112x over previous
#include <cuda_runtime.h>
#include <cuda_bf16.h>

#define N_NODES 100000
#define N_EDGES 1600000
#define IN_F 128
#define OUT_F 32
#define HEADS 2
#define NHF 64  // HEADS*OUT_F
#define SCAN_BLK 1024
#define N_SCAN_BLKS ((N_NODES + SCAN_BLK - 1) / SCAN_BLK)  // 98
#define GEMM_BLKS ((N_NODES + 63) / 64)                     // 1563
#define SCAT_BLKS (N_EDGES / 4 / 128)                       // 3125

// ---- scratch (device globals; no allocation) ----
__device__ float g_feat[N_NODES * NHF];   // [N][H][F] = [N][64]
__device__ float g_el[N_NODES * HEADS];
__device__ float g_er[N_NODES * HEADS];
__device__ float g_a[N_NODES];
__device__ float g_b[N_NODES];
__device__ float g_vfold[NHF];
__device__ float g_cfold;
// CSR-by-dst scratch
__device__ int g_deg[N_NODES];
__device__ int g_cur[N_NODES];
__device__ int g_off[N_NODES + 1];
__device__ int g_srcs[N_EDGES];
__device__ int g_blksum[N_SCAN_BLKS];

// ---- zero degree counters + fold MLP (block 0 does the fold) ----
__global__ void k_zero_fold(const float* __restrict__ W1, const float* __restrict__ b1,
                            const float* __restrict__ W2, const float* __restrict__ b2) {
    int i = blockIdx.x * blockDim.x + threadIdx.x;
    if (i < N_NODES) g_deg[i] = 0;
    if (blockIdx.x == 0) {
        int t = threadIdx.x;
        if (t < NHF) {
            float v = 0.f;
            #pragma unroll
            for (int j = 0; j < OUT_F; ++j) v += W1[t * OUT_F + j] * W2[j];
            g_vfold[t] = v;
        }
        if (t == 0) {
            float c = b2[0];
            for (int j = 0; j < OUT_F; ++j) c += b1[j] * W2[j];
            g_cfold = c;
        }
    }
}

// ---- histogram of dst (4 edges per thread, int4 loads) ----
__global__ void k_hist(const int* __restrict__ dst) {
    int i = blockIdx.x * blockDim.x + threadIdx.x;
    if (i * 4 >= N_EDGES) return;
    int4 d = *(const int4*)&dst[i * 4];
    atomicAdd(&g_deg[d.x], 1);
    atomicAdd(&g_deg[d.y], 1);
    atomicAdd(&g_deg[d.z], 1);
    atomicAdd(&g_deg[d.w], 1);
}

// ---- scan phase 1: per-block sums of g_deg ----
__global__ void k_scan1() {
    __shared__ int s[SCAN_BLK];
    int i = blockIdx.x * SCAN_BLK + threadIdx.x;
    s[threadIdx.x] = (i < N_NODES) ? g_deg[i] : 0;
    __syncthreads();
    #pragma unroll
    for (int off = SCAN_BLK / 2; off > 0; off >>= 1) {
        if (threadIdx.x < off) s[threadIdx.x] += s[threadIdx.x + off];
        __syncthreads();
    }
    if (threadIdx.x == 0) g_blksum[blockIdx.x] = s[0];
}

// ---- scan phase 2: exclusive scan of the 98 block sums (1 block, 128 thr) ----
__global__ void k_scan2() {
    __shared__ int s[128];
    int t = threadIdx.x;
    int v = (t < N_SCAN_BLKS) ? g_blksum[t] : 0;
    s[t] = v;
    __syncthreads();
    #pragma unroll
    for (int off = 1; off < 128; off <<= 1) {
        int u = (t >= off) ? s[t - off] : 0;
        __syncthreads();
        s[t] += u;
        __syncthreads();
    }
    if (t < N_SCAN_BLKS) g_blksum[t] = s[t] - v;  // exclusive prefix
    if (t == 127) g_off[N_NODES] = s[127];        // total edge count
}

// ---- scan phase 3: in-block exclusive scan + block offset -> g_off, g_cur ----
__global__ void k_scan3() {
    __shared__ int s[SCAN_BLK];
    int i = blockIdx.x * SCAN_BLK + threadIdx.x;
    int v = (i < N_NODES) ? g_deg[i] : 0;
    s[threadIdx.x] = v;
    __syncthreads();
    #pragma unroll
    for (int off = 1; off < SCAN_BLK; off <<= 1) {
        int u = (threadIdx.x >= off) ? s[threadIdx.x - off] : 0;
        __syncthreads();
        s[threadIdx.x] += u;
        __syncthreads();
    }
    if (i < N_NODES) {
        int excl = g_blksum[blockIdx.x] + s[threadIdx.x] - v;
        g_off[i] = excl;
        g_cur[i] = excl;
    }
}

// ---- fused: GEMM (blocks [0,GEMM_BLKS)) || scatter (remaining blocks) ----
// GEMM: feat = x @ W with el/er attention dots fused in the epilogue.
// Scatter: src ids into dst-sorted CSR order. Both are independent; the
// heterogeneous grid lets the HW overlap them in one launch (no streams).
__global__ void k_scatter_gemm(const int* __restrict__ src, const int* __restrict__ dst,
                               const float* __restrict__ x, const float* __restrict__ W,
                               const float* __restrict__ attn_l,
                               const float* __restrict__ attn_r) {
    __shared__ float Xs[64][68];
    __shared__ float Ws[64][64];
    if (blockIdx.x >= GEMM_BLKS) {
        // ---- scatter part: 128 threads x 4 edges ----
        int i = (blockIdx.x - GEMM_BLKS) * 128 + threadIdx.x;
        int4 s = *(const int4*)&src[i * 4];
        int4 d = *(const int4*)&dst[i * 4];
        g_srcs[atomicAdd(&g_cur[d.x], 1)] = s.x;
        g_srcs[atomicAdd(&g_cur[d.y], 1)] = s.y;
        g_srcs[atomicAdd(&g_cur[d.z], 1)] = s.z;
        g_srcs[atomicAdd(&g_cur[d.w], 1)] = s.w;
        return;
    }
    // ---- GEMM part ----
    const int block_row = blockIdx.x * 64;
    const int t = threadIdx.x;         // 128 threads
    const int tx = t & 15;
    const int ty = t >> 4;
    float acc[8][4];
    #pragma unroll
    for (int r = 0; r < 8; ++r)
        #pragma unroll
        for (int c = 0; c < 4; ++c) acc[r][c] = 0.f;

    for (int kt = 0; kt < 2; ++kt) {
        #pragma unroll
        for (int i = t; i < 64 * 16; i += 128) {
            int row = i >> 4, kq = i & 15;
            int gr = block_row + row;
            float4 v = make_float4(0.f, 0.f, 0.f, 0.f);
            if (gr < N_NODES)
                v = *(const float4*)&x[gr * IN_F + kt * 64 + kq * 4];
            Xs[kq * 4 + 0][row] = v.x;
            Xs[kq * 4 + 1][row] = v.y;
            Xs[kq * 4 + 2][row] = v.z;
            Xs[kq * 4 + 3][row] = v.w;
        }
        #pragma unroll
        for (int i = t; i < 64 * 16; i += 128) {
            int kk = i >> 4, nq = i & 15;
            *(float4*)&Ws[kk][nq * 4] =
                *(const float4*)&W[(kt * 64 + kk) * NHF + nq * 4];
        }
        __syncthreads();
        #pragma unroll 16
        for (int k = 0; k < 64; ++k) {
            float4 wv = *(const float4*)&Ws[k][tx * 4];
            float4 x0 = *(const float4*)&Xs[k][ty * 8];
            float4 x1 = *(const float4*)&Xs[k][ty * 8 + 4];
            float xr[8] = {x0.x, x0.y, x0.z, x0.w, x1.x, x1.y, x1.z, x1.w};
            #pragma unroll
            for (int r = 0; r < 8; ++r) {
                acc[r][0] += xr[r] * wv.x;
                acc[r][1] += xr[r] * wv.y;
                acc[r][2] += xr[r] * wv.z;
                acc[r][3] += xr[r] * wv.w;
            }
        }
        __syncthreads();
    }
    float4 al = *(const float4*)&attn_l[tx * 4];
    float4 ar = *(const float4*)&attn_r[tx * 4];
    float pel[8], per[8];
    #pragma unroll
    for (int r = 0; r < 8; ++r) {
        int gr = block_row + ty * 8 + r;
        if (gr < N_NODES)
            *(float4*)&g_feat[gr * NHF + tx * 4] =
                make_float4(acc[r][0], acc[r][1], acc[r][2], acc[r][3]);
        pel[r] = acc[r][0] * al.x + acc[r][1] * al.y + acc[r][2] * al.z + acc[r][3] * al.w;
        per[r] = acc[r][0] * ar.x + acc[r][1] * ar.y + acc[r][2] * ar.z + acc[r][3] * ar.w;
    }
    #pragma unroll
    for (int o = 1; o < 8; o <<= 1) {
        #pragma unroll
        for (int r = 0; r < 8; ++r) {
            pel[r] += __shfl_xor_sync(0xFFFFFFFFu, pel[r], o);
            per[r] += __shfl_xor_sync(0xFFFFFFFFu, per[r], o);
        }
    }
    if ((tx & 7) == 0) {
        int h = tx >> 3;
        #pragma unroll
        for (int r = 0; r < 8; ++r) {
            int gr = block_row + ty * 8 + r;
            if (gr < N_NODES) {
                g_el[gr * 2 + h] = pel[r];
                g_er[gr * 2 + h] = per[r];
            }
        }
    }
}

// ---- fused per-dst-node: softmax + aggregation + epilogue (warp per node) ----
// float2 lane mapping: lane L accumulates cols {2L, 2L+1} of the combined
// 64-float [head0|head1] feature row -> one LDG.64 per edge per lane.
__global__ void k_agg(const float* __restrict__ bias_gat) {
    int warp = (blockIdx.x * blockDim.x + threadIdx.x) >> 5;
    int lane = threadIdx.x & 31;
    if (warp >= N_NODES) return;
    const int n = warp;
    const int beg = g_off[n];
    const int end = g_off[n + 1];

    const float2 erd = *(const float2*)&g_er[n * 2];
    float2 acc = make_float2(0.f, 0.f);
    float den0 = 0.f, den1 = 0.f;

    for (int base = beg; base < end; base += 32) {
        const int cnt = min(32, end - base);
        // phase 1: each lane computes exp for one edge of this chunk
        int s = 0;
        float ex0 = 0.f, ex1 = 0.f;
        if (lane < cnt) {
            s = g_srcs[base + lane];
            float2 els = *(const float2*)&g_el[s * 2];
            float v0 = els.x + erd.x;
            float v1 = els.y + erd.y;
            v0 = v0 > 0.f ? v0 : 0.2f * v0;
            v1 = v1 > 0.f ? v1 : 0.2f * v1;
            ex0 = __expf(v0);
            ex1 = __expf(v1);
        }
        // phase 2: broadcast each edge, accumulate weighted feat (1 LDG.64/lane)
        for (int j = 0; j < cnt; ++j) {
            int sj = __shfl_sync(0xFFFFFFFFu, s, j);
            float e0 = __shfl_sync(0xFFFFFFFFu, ex0, j);
            float e1 = __shfl_sync(0xFFFFFFFFu, ex1, j);
            float2 f = *(const float2*)&g_feat[sj * NHF + 2 * lane];
            float w = (lane < 16) ? e0 : e1;
            acc.x = fmaf(w, f.x, acc.x);
            acc.y = fmaf(w, f.y, acc.y);
            den0 += e0;
            den1 += e1;
        }
    }

    // normalize per head; swap heads across the 16-lane halves
    float inv0 = (den0 > 0.f) ? 1.f / den0 : 0.f;
    float inv1 = (den1 > 0.f) ? 1.f / den1 : 0.f;
    float myinv = (lane < 16) ? inv0 : inv1;
    float rx = acc.x * myinv;
    float ry = acc.y * myinv;
    float ox = __shfl_xor_sync(0xFFFFFFFFu, rx, 16);
    float oy = __shfl_xor_sync(0xFFFFFFFFu, ry, 16);
    int c0 = 2 * (lane & 15);
    float2 bh0 = *(const float2*)&bias_gat[c0];        // bias[c0], bias[c0+1]
    float2 bh1 = *(const float2*)&bias_gat[32 + c0];   // bias[32+c0], ...
    float h0 = fmaxf(0.5f * (rx + ox + bh0.x + bh1.x), 0.f);
    float h1 = fmaxf(0.5f * (ry + oy + bh0.y + bh1.y), 0.f);
    float2 va = *(const float2*)&g_vfold[c0];
    float2 vb = *(const float2*)&g_vfold[32 + c0];
    float av = h0 * va.x + h1 * va.y;
    float bv = h0 * vb.x + h1 * vb.y;
    // lanes 16-31 hold duplicates; reduce within each 16-lane half only
    #pragma unroll
    for (int o = 1; o < 16; o <<= 1) {
        av += __shfl_xor_sync(0xFFFFFFFFu, av, o);
        bv += __shfl_xor_sync(0xFFFFFFFFu, bv, o);
    }
    if (lane == 0) { g_a[n] = av; g_b[n] = bv; }
}

// ---- per-edge final score (4 edges per thread) ----
__global__ void k_edge_score(const int* __restrict__ src, const int* __restrict__ dst,
                             float* __restrict__ out) {
    int i = blockIdx.x * blockDim.x + threadIdx.x;
    if (i * 4 >= N_EDGES) return;
    int4 s = *(const int4*)&src[i * 4];
    int4 d = *(const int4*)&dst[i * 4];
    float c = g_cfold;
    float4 r;
    r.x = g_a[s.x] + g_b[d.x] + c;
    r.y = g_a[s.y] + g_b[d.y] + c;
    r.z = g_a[s.z] + g_b[d.z] + c;
    r.w = g_a[s.w] + g_b[d.w] + c;
    *(float4*)&out[i * 4] = r;
}

extern "C" void kernel_launch(void* const* d_in, const int* in_sizes, int n_in,
                              void* d_out, int out_size) {
    const float* x       = (const float*)d_in[0];
    const float* W       = (const float*)d_in[1];
    const float* attn_l  = (const float*)d_in[2];
    const float* attn_r  = (const float*)d_in[3];
    const float* bias_gat= (const float*)d_in[4];
    const float* W1      = (const float*)d_in[5];
    const float* b1      = (const float*)d_in[6];
    const float* W2      = (const float*)d_in[7];
    const float* b2      = (const float*)d_in[8];
    const int*   src     = (const int*)d_in[9];
    const int*   dst     = (const int*)d_in[10];
    float* out = (float*)d_out;

    k_zero_fold<<<(N_NODES + 255) / 256, 256>>>(W1, b1, W2, b2);
    k_hist<<<(N_EDGES / 4 + 255) / 256, 256>>>(dst);
    k_scan1<<<N_SCAN_BLKS, SCAN_BLK>>>();
    k_scan2<<<1, 128>>>();
    k_scan3<<<N_SCAN_BLKS, SCAN_BLK>>>();
    k_scatter_gemm<<<GEMM_BLKS + SCAT_BLKS, 128>>>(src, dst, x, W, attn_l, attn_r);
    k_agg<<<(N_NODES * 32 + 255) / 256, 256>>>(bias_gat);
    k_edge_score<<<(N_EDGES / 4 + 255) / 256, 256>>>(src, dst, out);
}

// round 10
// speedup vs baseline: 2.2528x; 1.1193x over previous
#include <cuda_runtime.h>
#include <cuda_bf16.h>
#include <cuda_fp16.h>

#define N_NODES 100000
#define N_EDGES 1600000
#define IN_F 128
#define OUT_F 32
#define HEADS 2
#define NHF 64  // HEADS*OUT_F
#define SCAN_BLK 1024
#define N_SCAN_BLKS ((N_NODES + SCAN_BLK - 1) / SCAN_BLK)  // 98
#define GEMM_BLKS ((N_NODES + 63) / 64)                     // 1563
#define SCAT_BLKS (N_EDGES / 4 / 128)                       // 3125

// ---- scratch (device globals; zero-initialized at module load) ----
__device__ float g_feat[N_NODES * NHF];     // fp32 feat (attention dots source)
__device__ __half g_feat_h[N_NODES * NHF];  // fp16 copy for the agg gathers
__device__ float g_el[N_NODES * HEADS];
__device__ float g_er[N_NODES * HEADS];
__device__ float g_a[N_NODES];
__device__ float g_b[N_NODES];
__device__ float g_vfold[NHF];
__device__ float g_cfold;
// CSR-by-dst scratch. INVARIANT: g_deg is all-zero at entry of every launch
// sequence (zero-init at load; k_scan3 re-zeroes it each run).
__device__ int g_deg[N_NODES];
__device__ int g_cur[N_NODES];
__device__ int g_off[N_NODES + 1];
__device__ int g_srcs[N_EDGES];
__device__ int g_blksum[N_SCAN_BLKS];
__device__ int g_ticket;   // scan1 last-block election; reset each run

// ---- histogram of dst (4 edges/thread) + MLP fold in block 0 ----
__global__ void k_hist(const int* __restrict__ dst,
                       const float* __restrict__ W1, const float* __restrict__ b1,
                       const float* __restrict__ W2, const float* __restrict__ b2) {
    if (blockIdx.x == 0) {
        int t = threadIdx.x;
        if (t < NHF) {
            float v = 0.f;
            #pragma unroll
            for (int j = 0; j < OUT_F; ++j) v += W1[t * OUT_F + j] * W2[j];
            g_vfold[t] = v;
        }
        if (t == 0) {
            float c = b2[0];
            for (int j = 0; j < OUT_F; ++j) c += b1[j] * W2[j];
            g_cfold = c;
        }
    }
    int i = blockIdx.x * blockDim.x + threadIdx.x;
    if (i * 4 >= N_EDGES) return;
    int4 d = *(const int4*)&dst[i * 4];
    atomicAdd(&g_deg[d.x], 1);
    atomicAdd(&g_deg[d.y], 1);
    atomicAdd(&g_deg[d.z], 1);
    atomicAdd(&g_deg[d.w], 1);
}

// ---- scan phase 1+2 fused: per-block sums; last block scans the 98 sums ----
__global__ void k_scan1() {
    __shared__ int s[SCAN_BLK];
    __shared__ int is_last;
    int i = blockIdx.x * SCAN_BLK + threadIdx.x;
    s[threadIdx.x] = (i < N_NODES) ? g_deg[i] : 0;
    __syncthreads();
    #pragma unroll
    for (int off = SCAN_BLK / 2; off > 0; off >>= 1) {
        if (threadIdx.x < off) s[threadIdx.x] += s[threadIdx.x + off];
        __syncthreads();
    }
    if (threadIdx.x == 0) {
        g_blksum[blockIdx.x] = s[0];
        __threadfence();
        int t = atomicAdd(&g_ticket, 1);
        is_last = (t == gridDim.x - 1);
    }
    __syncthreads();
    if (!is_last) return;
    // last block: exclusive scan of the 98 block sums (first 128 threads)
    __shared__ int s2[128];
    int t = threadIdx.x;
    if (t < 128) {
        int v = (t < N_SCAN_BLKS) ? g_blksum[t] : 0;
        s2[t] = v;
        __syncthreads();
        #pragma unroll
        for (int off = 1; off < 128; off <<= 1) {
            int u = (t >= off) ? s2[t - off] : 0;
            __syncthreads();
            s2[t] += u;
            __syncthreads();
        }
        if (t < N_SCAN_BLKS) g_blksum[t] = s2[t] - v;  // exclusive prefix
        if (t == 127) g_off[N_NODES] = s2[127];
        if (t == 0) g_ticket = 0;                      // restore invariant
    } else {
        // keep the whole block in the barrier pattern
        __syncthreads();
        #pragma unroll
        for (int off = 1; off < 128; off <<= 1) { __syncthreads(); __syncthreads(); }
    }
}

// ---- scan phase 3: in-block exclusive scan + block offset; re-zero g_deg ----
__global__ void k_scan3() {
    __shared__ int s[SCAN_BLK];
    int i = blockIdx.x * SCAN_BLK + threadIdx.x;
    int v = (i < N_NODES) ? g_deg[i] : 0;
    s[threadIdx.x] = v;
    __syncthreads();
    #pragma unroll
    for (int off = 1; off < SCAN_BLK; off <<= 1) {
        int u = (threadIdx.x >= off) ? s[threadIdx.x - off] : 0;
        __syncthreads();
        s[threadIdx.x] += u;
        __syncthreads();
    }
    if (i < N_NODES) {
        int excl = g_blksum[blockIdx.x] + s[threadIdx.x] - v;
        g_off[i] = excl;
        g_cur[i] = excl;
        g_deg[i] = 0;   // restore the all-zero invariant for the next run
    }
}

// ---- fused: GEMM (blocks [0,GEMM_BLKS)) || scatter (remaining blocks) ----
__global__ void k_scatter_gemm(const int* __restrict__ src, const int* __restrict__ dst,
                               const float* __restrict__ x, const float* __restrict__ W,
                               const float* __restrict__ attn_l,
                               const float* __restrict__ attn_r) {
    __shared__ float Xs[64][68];
    __shared__ float Ws[64][64];
    if (blockIdx.x >= GEMM_BLKS) {
        // ---- scatter part: 128 threads x 4 edges ----
        int i = (blockIdx.x - GEMM_BLKS) * 128 + threadIdx.x;
        int4 s = *(const int4*)&src[i * 4];
        int4 d = *(const int4*)&dst[i * 4];
        g_srcs[atomicAdd(&g_cur[d.x], 1)] = s.x;
        g_srcs[atomicAdd(&g_cur[d.y], 1)] = s.y;
        g_srcs[atomicAdd(&g_cur[d.z], 1)] = s.z;
        g_srcs[atomicAdd(&g_cur[d.w], 1)] = s.w;
        return;
    }
    // ---- GEMM part ----
    const int block_row = blockIdx.x * 64;
    const int t = threadIdx.x;         // 128 threads
    const int tx = t & 15;
    const int ty = t >> 4;
    float acc[8][4];
    #pragma unroll
    for (int r = 0; r < 8; ++r)
        #pragma unroll
        for (int c = 0; c < 4; ++c) acc[r][c] = 0.f;

    for (int kt = 0; kt < 2; ++kt) {
        #pragma unroll
        for (int i = t; i < 64 * 16; i += 128) {
            int row = i >> 4, kq = i & 15;
            int gr = block_row + row;
            float4 v = make_float4(0.f, 0.f, 0.f, 0.f);
            if (gr < N_NODES)
                v = *(const float4*)&x[gr * IN_F + kt * 64 + kq * 4];
            Xs[kq * 4 + 0][row] = v.x;
            Xs[kq * 4 + 1][row] = v.y;
            Xs[kq * 4 + 2][row] = v.z;
            Xs[kq * 4 + 3][row] = v.w;
        }
        #pragma unroll
        for (int i = t; i < 64 * 16; i += 128) {
            int kk = i >> 4, nq = i & 15;
            *(float4*)&Ws[kk][nq * 4] =
                *(const float4*)&W[(kt * 64 + kk) * NHF + nq * 4];
        }
        __syncthreads();
        #pragma unroll 16
        for (int k = 0; k < 64; ++k) {
            float4 wv = *(const float4*)&Ws[k][tx * 4];
            float4 x0 = *(const float4*)&Xs[k][ty * 8];
            float4 x1 = *(const float4*)&Xs[k][ty * 8 + 4];
            float xr[8] = {x0.x, x0.y, x0.z, x0.w, x1.x, x1.y, x1.z, x1.w};
            #pragma unroll
            for (int r = 0; r < 8; ++r) {
                acc[r][0] += xr[r] * wv.x;
                acc[r][1] += xr[r] * wv.y;
                acc[r][2] += xr[r] * wv.z;
                acc[r][3] += xr[r] * wv.w;
            }
        }
        __syncthreads();
    }
    float4 al = *(const float4*)&attn_l[tx * 4];
    float4 ar = *(const float4*)&attn_r[tx * 4];
    float pel[8], per[8];
    #pragma unroll
    for (int r = 0; r < 8; ++r) {
        int gr = block_row + ty * 8 + r;
        if (gr < N_NODES) {
            // fp16 copy for agg gathers (half the L2 traffic per edge)
            __half2 h01 = __floats2half2_rn(acc[r][0], acc[r][1]);
            __half2 h23 = __floats2half2_rn(acc[r][2], acc[r][3]);
            *(__half2*)&g_feat_h[gr * NHF + tx * 4] = h01;
            *(__half2*)&g_feat_h[gr * NHF + tx * 4 + 2] = h23;
        }
        pel[r] = acc[r][0] * al.x + acc[r][1] * al.y + acc[r][2] * al.z + acc[r][3] * al.w;
        per[r] = acc[r][0] * ar.x + acc[r][1] * ar.y + acc[r][2] * ar.z + acc[r][3] * ar.w;
    }
    #pragma unroll
    for (int o = 1; o < 8; o <<= 1) {
        #pragma unroll
        for (int r = 0; r < 8; ++r) {
            pel[r] += __shfl_xor_sync(0xFFFFFFFFu, pel[r], o);
            per[r] += __shfl_xor_sync(0xFFFFFFFFu, per[r], o);
        }
    }
    if ((tx & 7) == 0) {
        int h = tx >> 3;
        #pragma unroll
        for (int r = 0; r < 8; ++r) {
            int gr = block_row + ty * 8 + r;
            if (gr < N_NODES) {
                g_el[gr * 2 + h] = pel[r];
                g_er[gr * 2 + h] = per[r];
            }
        }
    }
}

// ---- fused per-dst-node: softmax + aggregation + epilogue (warp per node) ----
// Lane L accumulates cols {2L,2L+1}; feat gathered as one half2 (4B) per lane
// -> one 128B line per edge. Attention weights stay fp32 end-to-end.
__global__ void k_agg(const float* __restrict__ bias_gat) {
    int warp = (blockIdx.x * blockDim.x + threadIdx.x) >> 5;
    int lane = threadIdx.x & 31;
    if (warp >= N_NODES) return;
    const int n = warp;
    const int beg = g_off[n];
    const int end = g_off[n + 1];

    const float2 erd = *(const float2*)&g_er[n * 2];
    float2 acc = make_float2(0.f, 0.f);
    float den0 = 0.f, den1 = 0.f;

    for (int base = beg; base < end; base += 32) {
        const int cnt = min(32, end - base);
        int s = 0;
        float ex0 = 0.f, ex1 = 0.f;
        if (lane < cnt) {
            s = g_srcs[base + lane];
            float2 els = *(const float2*)&g_el[s * 2];
            float v0 = els.x + erd.x;
            float v1 = els.y + erd.y;
            v0 = v0 > 0.f ? v0 : 0.2f * v0;
            v1 = v1 > 0.f ? v1 : 0.2f * v1;
            ex0 = __expf(v0);
            ex1 = __expf(v1);
        }
        for (int j = 0; j < cnt; ++j) {
            int sj = __shfl_sync(0xFFFFFFFFu, s, j);
            float e0 = __shfl_sync(0xFFFFFFFFu, ex0, j);
            float e1 = __shfl_sync(0xFFFFFFFFu, ex1, j);
            __half2 fh = *(const __half2*)&g_feat_h[sj * NHF + 2 * lane];
            float2 f = __half22float2(fh);
            float w = (lane < 16) ? e0 : e1;
            acc.x = fmaf(w, f.x, acc.x);
            acc.y = fmaf(w, f.y, acc.y);
            den0 += e0;
            den1 += e1;
        }
    }

    float inv0 = (den0 > 0.f) ? 1.f / den0 : 0.f;
    float inv1 = (den1 > 0.f) ? 1.f / den1 : 0.f;
    float myinv = (lane < 16) ? inv0 : inv1;
    float rx = acc.x * myinv;
    float ry = acc.y * myinv;
    float ox = __shfl_xor_sync(0xFFFFFFFFu, rx, 16);
    float oy = __shfl_xor_sync(0xFFFFFFFFu, ry, 16);
    int c0 = 2 * (lane & 15);
    float2 bh0 = *(const float2*)&bias_gat[c0];
    float2 bh1 = *(const float2*)&bias_gat[32 + c0];
    float h0 = fmaxf(0.5f * (rx + ox + bh0.x + bh1.x), 0.f);
    float h1 = fmaxf(0.5f * (ry + oy + bh0.y + bh1.y), 0.f);
    float2 va = *(const float2*)&g_vfold[c0];
    float2 vb = *(const float2*)&g_vfold[32 + c0];
    float av = h0 * va.x + h1 * va.y;
    float bv = h0 * vb.x + h1 * vb.y;
    #pragma unroll
    for (int o = 1; o < 16; o <<= 1) {
        av += __shfl_xor_sync(0xFFFFFFFFu, av, o);
        bv += __shfl_xor_sync(0xFFFFFFFFu, bv, o);
    }
    if (lane == 0) { g_a[n] = av; g_b[n] = bv; }
}

// ---- per-edge final score (4 edges per thread) ----
__global__ void k_edge_score(const int* __restrict__ src, const int* __restrict__ dst,
                             float* __restrict__ out) {
    int i = blockIdx.x * blockDim.x + threadIdx.x;
    if (i * 4 >= N_EDGES) return;
    int4 s = *(const int4*)&src[i * 4];
    int4 d = *(const int4*)&dst[i * 4];
    float c = g_cfold;
    float4 r;
    r.x = g_a[s.x] + g_b[d.x] + c;
    r.y = g_a[s.y] + g_b[d.y] + c;
    r.z = g_a[s.z] + g_b[d.z] + c;
    r.w = g_a[s.w] + g_b[d.w] + c;
    *(float4*)&out[i * 4] = r;
}

extern "C" void kernel_launch(void* const* d_in, const int* in_sizes, int n_in,
                              void* d_out, int out_size) {
    const float* x       = (const float*)d_in[0];
    const float* W       = (const float*)d_in[1];
    const float* attn_l  = (const float*)d_in[2];
    const float* attn_r  = (const float*)d_in[3];
    const float* bias_gat= (const float*)d_in[4];
    const float* W1      = (const float*)d_in[5];
    const float* b1      = (const float*)d_in[6];
    const float* W2      = (const float*)d_in[7];
    const float* b2      = (const float*)d_in[8];
    const int*   src     = (const int*)d_in[9];
    const int*   dst     = (const int*)d_in[10];
    float* out = (float*)d_out;

    k_hist<<<(N_EDGES / 4 + 255) / 256, 256>>>(dst, W1, b1, W2, b2);
    k_scan1<<<N_SCAN_BLKS, SCAN_BLK>>>();
    k_scan3<<<N_SCAN_BLKS, SCAN_BLK>>>();
    k_scatter_gemm<<<GEMM_BLKS + SCAT_BLKS, 128>>>(src, dst, x, W, attn_l, attn_r);
    k_agg<<<(N_NODES * 32 + 255) / 256, 256>>>(bias_gat);
    k_edge_score<<<(N_EDGES / 4 + 255) / 256, 256>>>(src, dst, out);
}